// round 6
// baseline (speedup 1.0000x reference)
#include <cuda_runtime.h>
#include <cuda_bf16.h>
#include <cstdint>

// ---------------------------------------------------------------------------
// MultiAxisAttention (Swin window attention) — HMMA tf32 everywhere.
//   prep: xr = rna(x) (pad rows zeroed), weights rna-rounded
//   K1:   qkv = xr @ wqkv_r     (tf32 mma, 3-stage cp.async, 1 sync/stage)
//   K2:   attention: QK^T and PV both on tensor pipe (m16n8k8.tf32)
//   K3:   out = att @ wout_r
// ---------------------------------------------------------------------------

#define M_REAL 153664            // 16*196*49
#define M_PAD  153728            // 1201*128
#define NWIN   3136
#define HEADS  16
#define WIN    49
#define KDIM   512

__device__ float g_qkv[236027904];    // M_REAL*1536
__device__ float g_att[78708736];     // M_PAD*512 (pad rows zeroed)
__device__ float g_xr [78708736];     // M_PAD*512 (tf32-rounded, pad zeroed)
__device__ float g_wqkv_r[786432];    // 512*1536 rounded
__device__ float g_wout_r[262144];    // 512*512  rounded

// ------------------------------ helpers -----------------------------------
__device__ __forceinline__ float tf32r(float f) {
    unsigned u;
    asm("cvt.rna.tf32.f32 %0, %1;" : "=r"(u) : "f"(f));
    return __uint_as_float(u);
}
__device__ __forceinline__ uint32_t smem_u32(const void* p) {
    uint32_t a;
    asm("{ .reg .u64 t; cvta.to.shared.u64 t, %1; cvt.u32.u64 %0, t; }"
        : "=r"(a) : "l"(p));
    return a;
}
__device__ __forceinline__ void cp16(uint32_t dst, const void* src) {
    asm volatile("cp.async.cg.shared.global [%0], [%1], 16;\n"
                 :: "r"(dst), "l"(src));
}
#define CP_COMMIT() asm volatile("cp.async.commit_group;\n" ::: "memory")
#define CP_WAIT(n)  asm volatile("cp.async.wait_group %0;\n" :: "n"(n) : "memory")

__device__ __forceinline__ void mma_tf32(float* d, const unsigned* a, const unsigned* b) {
    asm volatile(
        "mma.sync.aligned.m16n8k8.row.col.f32.tf32.tf32.f32 "
        "{%0,%1,%2,%3}, {%4,%5,%6,%7}, {%8,%9}, {%0,%1,%2,%3};\n"
        : "+f"(d[0]), "+f"(d[1]), "+f"(d[2]), "+f"(d[3])
        : "r"(a[0]), "r"(a[1]), "r"(a[2]), "r"(a[3]),
          "r"(b[0]), "r"(b[1]));
}

// ------------------------------- GEMM (tf32) ------------------------------
// block 128x128, BK=32, 4 warps (2x2), warp tile 64x64.
// 3-stage cp.async ring, single __syncthreads per stage.
// Inputs tf32-pre-rounded. A: [M,512] row-major. B: [512,N] row-major.
#define BM 128
#define BN 128
#define BK 32
#define AST 36
#define BST 136
#define AS_FLOATS (BM * AST)          // 4608
#define BS_FLOATS (BK * BST)          // 4352
#define STG_FLOATS (AS_FLOATS + BS_FLOATS)            // 8960
#define GSMEM_BYTES (3 * STG_FLOATS * 4)              // 107520

__global__ void __launch_bounds__(128)
gemm_tf32(const float* __restrict__ A, const float* __restrict__ B,
          float* __restrict__ C, int Mreal, int N)
{
    extern __shared__ float sm[];

    const int tid  = threadIdx.x;
    const int lane = tid & 31;
    const int warp = tid >> 5;
    const int wm   = warp >> 1;
    const int wn   = warp & 1;
    const int grp  = lane >> 2;
    const int tg   = lane & 3;

    const int m0 = blockIdx.y * BM;
    const int n0 = blockIdx.x * BN;

    // coalesced fill geometry
    const int arow = tid >> 3;             // 0..15
    const int achk = (tid & 7) << 2;       // 0,4,..,28
    const float*  ag0  = A + (size_t)(m0 + arow) * KDIM + achk;
    const uint32_t asm0 = smem_u32(sm) + (uint32_t)(arow * AST + achk) * 4;
    const int brow = tid >> 5;             // 0..3
    const int bchk = (tid & 31) << 2;      // 0..124
    const float*  bg0  = B + (size_t)brow * N + n0 + bchk;
    const uint32_t bsm0 = smem_u32(sm) + (uint32_t)(AS_FLOATS + brow * BST + bchk) * 4;

    float acc[4][8][4];
    #pragma unroll
    for (int i = 0; i < 4; i++)
        #pragma unroll
        for (int j = 0; j < 8; j++)
            #pragma unroll
            for (int l = 0; l < 4; l++) acc[i][j][l] = 0.f;

    const int T = KDIM / BK;   // 16

    // prologue: stages 0,1
    #pragma unroll
    for (int s = 0; s < 2; s++) {
        const uint32_t ad = asm0 + (uint32_t)(s * STG_FLOATS) * 4;
        const uint32_t bd = bsm0 + (uint32_t)(s * STG_FLOATS) * 4;
        const float* ag = ag0 + s * BK;
        const float* bg = bg0 + (size_t)s * BK * N;
        #pragma unroll
        for (int p = 0; p < 8; p++)
            cp16(ad + (uint32_t)(p * 16 * AST) * 4, ag + (size_t)p * 16 * KDIM);
        #pragma unroll
        for (int p = 0; p < 8; p++)
            cp16(bd + (uint32_t)(p * 4 * BST) * 4, bg + (size_t)p * 4 * N);
        CP_COMMIT();
    }

    int bc = 0;   // t % 3
    int pb = 2;   // (t+2) % 3
    for (int t = 0; t < T; ++t) {
        if (t < T - 1) { CP_WAIT(1); } else { CP_WAIT(0); }
        __syncthreads();

        if (t + 2 < T) {
            const int kb = (t + 2) * BK;
            const uint32_t ad = asm0 + (uint32_t)(pb * STG_FLOATS) * 4;
            const uint32_t bd = bsm0 + (uint32_t)(pb * STG_FLOATS) * 4;
            const float* ag = ag0 + kb;
            const float* bg = bg0 + (size_t)kb * N;
            #pragma unroll
            for (int p = 0; p < 8; p++)
                cp16(ad + (uint32_t)(p * 16 * AST) * 4, ag + (size_t)p * 16 * KDIM);
            #pragma unroll
            for (int p = 0; p < 8; p++)
                cp16(bd + (uint32_t)(p * 4 * BST) * 4, bg + (size_t)p * 4 * N);
            CP_COMMIT();
        }

        const float* Ab = sm + bc * STG_FLOATS;
        const float* Bb = Ab + AS_FLOATS;
        #pragma unroll
        for (int ks = 0; ks < 4; ks++) {
            const int kk = ks * 8;
            unsigned af[4][4], bf[8][2];
            #pragma unroll
            for (int mt = 0; mt < 4; mt++) {
                int mr = wm * 64 + mt * 16 + grp;
                af[mt][0] = __float_as_uint(Ab[ mr      * AST + kk + tg]);
                af[mt][1] = __float_as_uint(Ab[(mr + 8) * AST + kk + tg]);
                af[mt][2] = __float_as_uint(Ab[ mr      * AST + kk + tg + 4]);
                af[mt][3] = __float_as_uint(Ab[(mr + 8) * AST + kk + tg + 4]);
            }
            #pragma unroll
            for (int nt = 0; nt < 8; nt++) {
                int nc = wn * 64 + nt * 8 + grp;
                bf[nt][0] = __float_as_uint(Bb[(kk + tg)     * BST + nc]);
                bf[nt][1] = __float_as_uint(Bb[(kk + tg + 4) * BST + nc]);
            }
            #pragma unroll
            for (int mt = 0; mt < 4; mt++)
                #pragma unroll
                for (int nt = 0; nt < 8; nt++)
                    mma_tf32(acc[mt][nt], af[mt], bf[nt]);
        }

        bc = (bc == 2) ? 0 : bc + 1;
        pb = (pb == 2) ? 0 : pb + 1;
    }

    #pragma unroll
    for (int mt = 0; mt < 4; mt++) {
        #pragma unroll
        for (int nt = 0; nt < 8; nt++) {
            int r0 = m0 + wm * 64 + mt * 16 + grp;
            int c  = n0 + wn * 64 + nt * 8 + tg * 2;
            if (r0 < Mreal)
                *(float2*)(C + (size_t)r0 * N + c) =
                    make_float2(acc[mt][nt][0], acc[mt][nt][1]);
            if (r0 + 8 < Mreal)
                *(float2*)(C + (size_t)(r0 + 8) * N + c) =
                    make_float2(acc[mt][nt][2], acc[mt][nt][3]);
        }
    }
}

// ------------------------------ prep kernels -------------------------------
__global__ void round_pad(const float* __restrict__ x, float* __restrict__ xr,
                          long nreal, long ntot)
{
    long i = (long)blockIdx.x * blockDim.x + threadIdx.x;
    if (i < ntot) xr[i] = (i < nreal) ? tf32r(x[i]) : 0.f;
}

__global__ void round_copy(const float* __restrict__ w, float* __restrict__ wr, int n)
{
    int i = blockIdx.x * blockDim.x + threadIdx.x;
    if (i < n) wr[i] = tf32r(w[i]);
}

__global__ void zero_fill(float* __restrict__ p, int n)
{
    int i = blockIdx.x * blockDim.x + threadIdx.x;
    if (i < n) p[i] = 0.f;
}

// ----------------------------- attention (HMMA) ----------------------------
// one CTA per (window, head); 128 threads (4 warps).
// QK^T: [64x56] = Q[64x32] @ K^T  (m16n8k8.tf32, warp wm owns 16 rows)
// PV:   [64x32] = P[64x56] @ V[56x32]
// All cross-warp data produced before the single __syncthreads; P rows are
// warp-local (produced and consumed by the same warp).
#define QST 36    // Qs  [64][36]  banks 4*grp+tg
#define KST 72    // KsT [32][72]  banks 8*tg+grp
#define VST 40    // Vs  [56][40]  banks 8*tg+grp
#define PST 60    // Ps  [64][60]  banks 28*grp+tg
#define BMT 56    // Bm  [64][56]
#define OFF_Q   0
#define OFF_KT  (OFF_Q  + 64 * QST)
#define OFF_V   (OFF_KT + 32 * KST)
#define OFF_P   (OFF_V  + 56 * VST)
#define OFF_BM  (OFF_P  + 64 * PST)
#define OFF_INV (OFF_BM + 64 * BMT)
#define ASMEM_FLOATS (OFF_INV + 64)     // 14400 floats = 57600 B

__global__ void __launch_bounds__(128)
attn_mma(const float* __restrict__ qkv,
         const float* __restrict__ bias_table,
         float* __restrict__ att)
{
    extern __shared__ float sa[];
    float* Qs  = sa + OFF_Q;
    float* KsT = sa + OFF_KT;
    float* Vs  = sa + OFF_V;
    float* Ps  = sa + OFF_P;
    float* Bm  = sa + OFF_BM;
    float* inv = sa + OFF_INV;

    const int h  = blockIdx.x & 15;
    const int bw = blockIdx.x >> 4;
    const int tid  = threadIdx.x;
    const int lane = tid & 31;
    const int wm   = tid >> 5;          // warp id = m-tile (16 rows each)
    const int grp  = lane >> 2;
    const int tg   = lane & 3;

    const float* base = qkv + (size_t)bw * WIN * 1536 + h * 32;
    const float SCALE = 0.17677669529663687f;

    // ---- fill Q (scaled+rounded) and V (rounded) ----
    for (int l = tid; l < WIN * 32; l += 128) {
        int i = l >> 5, d = l & 31;
        const float* row = base + (size_t)i * 1536;
        Qs[i * QST + d] = tf32r(row[d] * SCALE);
        Vs[i * VST + d] = tf32r(row[1024 + d]);
    }
    // ---- K transposed: KsT[d][j] ----
    {
        int d = tid >> 2, jq = tid & 3;
        const float* kcol = base + 512 + d;
        for (int j = jq; j < WIN; j += 4)
            KsT[d * KST + j] = tf32r(kcol[(size_t)j * 1536]);
    }
    // ---- zero V pad rows (j = 49..55) ----
    for (int l = tid; l < 7 * 32; l += 128) {
        int j = WIN + (l >> 5), d = l & 31;
        Vs[j * VST + d] = 0.f;
    }
    // ---- bias matrix Bm[i][j], i,j < 49 ----
    for (int l = tid; l < WIN * WIN; l += 128) {
        int i = l / WIN, j = l - i * WIN;
        int ri = i / 7, ci = i - ri * 7;
        int rj = j / 7, cj = j - rj * 7;
        Bm[i * BMT + j] =
            bias_table[((ri - rj + 6) * 13 + (ci - cj + 6)) * HEADS + h];
    }
    __syncthreads();

    const int i0 = wm * 16 + grp;
    const int i1 = i0 + 8;

    // ---- QK^T: c[7][4], rows i0/i1, cols nt*8 + 2tg (+1) ----
    float c[7][4];
    #pragma unroll
    for (int nt = 0; nt < 7; nt++)
        #pragma unroll
        for (int l = 0; l < 4; l++) c[nt][l] = 0.f;

    #pragma unroll
    for (int ks = 0; ks < 4; ks++) {
        const int kk = ks * 8;
        unsigned a[4];
        a[0] = __float_as_uint(Qs[i0 * QST + kk + tg]);
        a[1] = __float_as_uint(Qs[i1 * QST + kk + tg]);
        a[2] = __float_as_uint(Qs[i0 * QST + kk + tg + 4]);
        a[3] = __float_as_uint(Qs[i1 * QST + kk + tg + 4]);
        #pragma unroll
        for (int nt = 0; nt < 7; nt++) {
            unsigned b[2];
            b[0] = __float_as_uint(KsT[(kk + tg)     * KST + nt * 8 + grp]);
            b[1] = __float_as_uint(KsT[(kk + tg + 4) * KST + nt * 8 + grp]);
            mma_tf32(c[nt], a, b);
        }
    }

    // ---- softmax numerators -> Ps (tf32), row sums via tg-butterfly ----
    float s01 = 0.f, s23 = 0.f;
    #pragma unroll
    for (int nt = 0; nt < 7; nt++) {
        const int j0 = nt * 8 + 2 * tg;
        float2 b0 = *(const float2*)(Bm + i0 * BMT + j0);
        float2 b1 = *(const float2*)(Bm + i1 * BMT + j0);
        float e00 = (j0     < WIN) ? __expf(c[nt][0] + b0.x) : 0.f;
        float e01 = (j0 + 1 < WIN) ? __expf(c[nt][1] + b0.y) : 0.f;
        float e10 = (j0     < WIN) ? __expf(c[nt][2] + b1.x) : 0.f;
        float e11 = (j0 + 1 < WIN) ? __expf(c[nt][3] + b1.y) : 0.f;
        s01 += e00 + e01;
        s23 += e10 + e11;
        *(float2*)(Ps + i0 * PST + j0) = make_float2(tf32r(e00), tf32r(e01));
        *(float2*)(Ps + i1 * PST + j0) = make_float2(tf32r(e10), tf32r(e11));
    }
    s01 += __shfl_xor_sync(0xFFFFFFFFu, s01, 1);
    s01 += __shfl_xor_sync(0xFFFFFFFFu, s01, 2);
    s23 += __shfl_xor_sync(0xFFFFFFFFu, s23, 1);
    s23 += __shfl_xor_sync(0xFFFFFFFFu, s23, 2);
    if (tg == 0) {
        inv[i0] = 1.f / s01;
        inv[i1] = 1.f / s23;
    }
    __syncwarp();

    // ---- PV: o[4][4] = P[64x56] @ V[56x32] (warp-local P rows) ----
    float o[4][4];
    #pragma unroll
    for (int nt = 0; nt < 4; nt++)
        #pragma unroll
        for (int l = 0; l < 4; l++) o[nt][l] = 0.f;

    #pragma unroll
    for (int ks = 0; ks < 7; ks++) {
        const int kk = ks * 8;
        unsigned a[4];
        a[0] = __float_as_uint(Ps[i0 * PST + kk + tg]);
        a[1] = __float_as_uint(Ps[i1 * PST + kk + tg]);
        a[2] = __float_as_uint(Ps[i0 * PST + kk + tg + 4]);
        a[3] = __float_as_uint(Ps[i1 * PST + kk + tg + 4]);
        #pragma unroll
        for (int nt = 0; nt < 4; nt++) {
            unsigned b[2];
            b[0] = __float_as_uint(Vs[(kk + tg)     * VST + nt * 8 + grp]);
            b[1] = __float_as_uint(Vs[(kk + tg + 4) * VST + nt * 8 + grp]);
            mma_tf32(o[nt], a, b);
        }
    }

    const float v0 = inv[i0];
    const float v1 = inv[i1];
    float* obase = att + (size_t)bw * WIN * 512 + h * 32;
    #pragma unroll
    for (int nt = 0; nt < 4; nt++) {
        const int d0 = nt * 8 + 2 * tg;
        if (i0 < WIN)
            *(float2*)(obase + (size_t)i0 * 512 + d0) =
                make_float2(tf32r(o[nt][0] * v0), tf32r(o[nt][1] * v0));
        if (i1 < WIN)
            *(float2*)(obase + (size_t)i1 * 512 + d0) =
                make_float2(tf32r(o[nt][2] * v1), tf32r(o[nt][3] * v1));
    }
}

// --------------------------------- launcher --------------------------------
extern "C" void kernel_launch(void* const* d_in, const int* in_sizes, int n_in,
                              void* d_out, int out_size)
{
    const float* x          = (const float*)d_in[0];
    const float* w_qkv      = (const float*)d_in[1];
    const float* bias_table = (const float*)d_in[2];
    const float* w_out      = (const float*)d_in[3];
    float* out = (float*)d_out;

    float *qkv, *att, *xr, *wqkv_r, *wout_r;
    cudaGetSymbolAddress((void**)&qkv,    g_qkv);
    cudaGetSymbolAddress((void**)&att,    g_att);
    cudaGetSymbolAddress((void**)&xr,     g_xr);
    cudaGetSymbolAddress((void**)&wqkv_r, g_wqkv_r);
    cudaGetSymbolAddress((void**)&wout_r, g_wout_r);

    cudaFuncSetAttribute(gemm_tf32, cudaFuncAttributeMaxDynamicSharedMemorySize,
                         GSMEM_BYTES);
    cudaFuncSetAttribute(attn_mma, cudaFuncAttributeMaxDynamicSharedMemorySize,
                         ASMEM_FLOATS * 4);

    const long nreal = (long)M_REAL * 512;
    const long ntot  = (long)M_PAD  * 512;

    round_pad<<<(int)((ntot + 255) / 256), 256>>>(x, xr, nreal, ntot);
    round_copy<<<(786432 + 255) / 256, 256>>>(w_qkv, wqkv_r, 786432);
    round_copy<<<(262144 + 255) / 256, 256>>>(w_out, wout_r, 262144);
    zero_fill<<<(64 * 512 + 255) / 256, 256>>>(att + nreal, 64 * 512);

    // K1: qkv = xr @ wqkv_r
    gemm_tf32<<<dim3(1536 / BN, M_PAD / BM), 128, GSMEM_BYTES>>>(
        xr, wqkv_r, qkv, M_REAL, 1536);

    // K2: attention (tensor-core QK^T and PV)
    attn_mma<<<NWIN * HEADS, 128, ASMEM_FLOATS * 4>>>(qkv, bias_table, att);

    // K3: out = att @ wout_r
    gemm_tf32<<<dim3(512 / BN, M_PAD / BM), 128, GSMEM_BYTES>>>(
        att, wout_r, out, M_REAL, 512);
}

// round 7
// speedup vs baseline: 1.5965x; 1.5965x over previous
#include <cuda_runtime.h>
#include <cuda_bf16.h>
#include <cstdint>

// ---------------------------------------------------------------------------
// MultiAxisAttention (Swin window attention) — HMMA tf32 everywhere.
//   prep: xr = rna(x) (pad rows zeroed), weights rna-rounded
//   K1:   qkv = xr @ wqkv_r     (tf32 mma, cp.async dbl-buffer — R5 proven)
//   K2:   attention on tensor pipe; coalesced fills, no bias matrix
//   K3:   out = att @ wout_r
// ---------------------------------------------------------------------------

#define M_REAL 153664            // 16*196*49
#define M_PAD  153728            // 1201*128
#define NWIN   3136
#define HEADS  16
#define WIN    49
#define KDIM   512

__device__ float g_qkv[236027904];    // M_REAL*1536
__device__ float g_att[78708736];     // M_PAD*512 (pad rows zeroed)
__device__ float g_xr [78708736];     // M_PAD*512 (tf32-rounded, pad zeroed)
__device__ float g_wqkv_r[786432];    // 512*1536 rounded
__device__ float g_wout_r[262144];    // 512*512  rounded

// ------------------------------ helpers -----------------------------------
__device__ __forceinline__ float tf32r(float f) {
    unsigned u;
    asm("cvt.rna.tf32.f32 %0, %1;" : "=r"(u) : "f"(f));
    return __uint_as_float(u);
}
__device__ __forceinline__ uint32_t smem_u32(const void* p) {
    uint32_t a;
    asm("{ .reg .u64 t; cvta.to.shared.u64 t, %1; cvt.u32.u64 %0, t; }"
        : "=r"(a) : "l"(p));
    return a;
}
__device__ __forceinline__ void cp16(uint32_t dst, const void* src) {
    asm volatile("cp.async.cg.shared.global [%0], [%1], 16;\n"
                 :: "r"(dst), "l"(src));
}
#define CP_COMMIT() asm volatile("cp.async.commit_group;\n" ::: "memory")
#define CP_WAIT(n)  asm volatile("cp.async.wait_group %0;\n" :: "n"(n) : "memory")

__device__ __forceinline__ void mma_tf32(float* d, const unsigned* a, const unsigned* b) {
    asm volatile(
        "mma.sync.aligned.m16n8k8.row.col.f32.tf32.tf32.f32 "
        "{%0,%1,%2,%3}, {%4,%5,%6,%7}, {%8,%9}, {%0,%1,%2,%3};\n"
        : "+f"(d[0]), "+f"(d[1]), "+f"(d[2]), "+f"(d[3])
        : "r"(a[0]), "r"(a[1]), "r"(a[2]), "r"(a[3]),
          "r"(b[0]), "r"(b[1]));
}

// ------------------------------- GEMM (tf32) ------------------------------
// R5-proven: block 128x128, BK=32, 4 warps, warp tile 64x64, dbl-buffer.
#define BM 128
#define BN 128
#define BK 32
#define AST 36
#define BST 136
#define AS_FLOATS (BM * AST)          // 4608
#define BS_FLOATS (BK * BST)          // 4352
#define SMEM_FLOATS (2 * AS_FLOATS + 2 * BS_FLOATS)   // 17920 -> 71680 B

__global__ void __launch_bounds__(128)
gemm_tf32(const float* __restrict__ A, const float* __restrict__ B,
          float* __restrict__ C, int Mreal, int N)
{
    extern __shared__ float sm[];
    float* As = sm;
    float* Bs = sm + 2 * AS_FLOATS;

    const int tid  = threadIdx.x;
    const int lane = tid & 31;
    const int warp = tid >> 5;
    const int wm   = warp >> 1;
    const int wn   = warp & 1;
    const int grp  = lane >> 2;
    const int tg   = lane & 3;

    const int m0 = blockIdx.y * BM;
    const int n0 = blockIdx.x * BN;

    const int arow = tid >> 3;
    const int achk = (tid & 7) << 2;
    const float*  ag0  = A + (size_t)(m0 + arow) * KDIM + achk;
    const uint32_t asm0 = smem_u32(As) + (uint32_t)(arow * AST + achk) * 4;
    const int brow = tid >> 5;
    const int bchk = (tid & 31) << 2;
    const float*  bg0  = B + (size_t)brow * N + n0 + bchk;
    const uint32_t bsm0 = smem_u32(Bs) + (uint32_t)(brow * BST + bchk) * 4;

    float acc[4][8][4];
    #pragma unroll
    for (int i = 0; i < 4; i++)
        #pragma unroll
        for (int j = 0; j < 8; j++)
            #pragma unroll
            for (int l = 0; l < 4; l++) acc[i][j][l] = 0.f;

    const int T = KDIM / BK;   // 16

    #pragma unroll
    for (int p = 0; p < 8; p++)
        cp16(asm0 + (uint32_t)(p * 16 * AST) * 4, ag0 + (size_t)p * 16 * KDIM);
    #pragma unroll
    for (int p = 0; p < 8; p++)
        cp16(bsm0 + (uint32_t)(p * 4 * BST) * 4, bg0 + (size_t)p * 4 * N);
    CP_COMMIT();

    for (int t = 0; t < T; ++t) {
        const int buf = t & 1;

        if (t + 1 < T) {
            const int nb = (t + 1) & 1;
            const int kb = (t + 1) * BK;
            const uint32_t ad = asm0 + (uint32_t)nb * AS_FLOATS * 4;
            const uint32_t bd = bsm0 + (uint32_t)nb * BS_FLOATS * 4;
            const float* ag = ag0 + kb;
            const float* bg = bg0 + (size_t)kb * N;
            #pragma unroll
            for (int p = 0; p < 8; p++)
                cp16(ad + (uint32_t)(p * 16 * AST) * 4, ag + (size_t)p * 16 * KDIM);
            #pragma unroll
            for (int p = 0; p < 8; p++)
                cp16(bd + (uint32_t)(p * 4 * BST) * 4, bg + (size_t)p * 4 * N);
            CP_COMMIT();
            CP_WAIT(1);
        } else {
            CP_WAIT(0);
        }
        __syncthreads();

        const float* Ab = As + buf * AS_FLOATS;
        const float* Bb = Bs + buf * BS_FLOATS;
        #pragma unroll
        for (int ks = 0; ks < 4; ks++) {
            const int kk = ks * 8;
            unsigned af[4][4], bf[8][2];
            #pragma unroll
            for (int mt = 0; mt < 4; mt++) {
                int mr = wm * 64 + mt * 16 + grp;
                af[mt][0] = __float_as_uint(Ab[ mr      * AST + kk + tg]);
                af[mt][1] = __float_as_uint(Ab[(mr + 8) * AST + kk + tg]);
                af[mt][2] = __float_as_uint(Ab[ mr      * AST + kk + tg + 4]);
                af[mt][3] = __float_as_uint(Ab[(mr + 8) * AST + kk + tg + 4]);
            }
            #pragma unroll
            for (int nt = 0; nt < 8; nt++) {
                int nc = wn * 64 + nt * 8 + grp;
                bf[nt][0] = __float_as_uint(Bb[(kk + tg)     * BST + nc]);
                bf[nt][1] = __float_as_uint(Bb[(kk + tg + 4) * BST + nc]);
            }
            #pragma unroll
            for (int mt = 0; mt < 4; mt++)
                #pragma unroll
                for (int nt = 0; nt < 8; nt++)
                    mma_tf32(acc[mt][nt], af[mt], bf[nt]);
        }
        __syncthreads();
    }

    #pragma unroll
    for (int mt = 0; mt < 4; mt++) {
        #pragma unroll
        for (int nt = 0; nt < 8; nt++) {
            int r0 = m0 + wm * 64 + mt * 16 + grp;
            int c  = n0 + wn * 64 + nt * 8 + tg * 2;
            if (r0 < Mreal)
                *(float2*)(C + (size_t)r0 * N + c) =
                    make_float2(acc[mt][nt][0], acc[mt][nt][1]);
            if (r0 + 8 < Mreal)
                *(float2*)(C + (size_t)(r0 + 8) * N + c) =
                    make_float2(acc[mt][nt][2], acc[mt][nt][3]);
        }
    }
}

// ------------------------------ prep kernels -------------------------------
__global__ void round_pad(const float* __restrict__ x, float* __restrict__ xr,
                          long nreal, long ntot)
{
    long i = (long)blockIdx.x * blockDim.x + threadIdx.x;
    if (i < ntot) xr[i] = (i < nreal) ? tf32r(x[i]) : 0.f;
}

__global__ void round_copy(const float* __restrict__ w, float* __restrict__ wr, int n)
{
    int i = blockIdx.x * blockDim.x + threadIdx.x;
    if (i < n) wr[i] = tf32r(w[i]);
}

__global__ void zero_fill(float* __restrict__ p, int n)
{
    int i = blockIdx.x * blockDim.x + threadIdx.x;
    if (i < n) p[i] = 0.f;
}

// ----------------------------- attention (HMMA) ----------------------------
// one CTA per (window, head); 128 threads (4 warps, warp = 16 query rows).
// QK^T [64x56] and PV [64x32] on m16n8k8.tf32. K kept ROW-major (the col-major
// B fragment is just an indexing pattern); bias via bs[169] + (j*37)>>8 div-7.
#define QST 36
#define KST 36
#define VST 40
#define PST 60

__device__ __forceinline__ int div7(int v) { return (v * 37) >> 8; }  // exact 0..55

__global__ void __launch_bounds__(128)
attn_mma(const float* __restrict__ qkv,
         const float* __restrict__ bias_table,
         float* __restrict__ att)
{
    __shared__ float Qs[64 * QST];
    __shared__ float Ks[56 * KST];
    __shared__ float Vs[56 * VST];
    __shared__ float Ps[64 * PST];
    __shared__ float bs[176];
    __shared__ float inv[64];

    const int h  = blockIdx.x & 15;
    const int bw = blockIdx.x >> 4;
    const int tid  = threadIdx.x;
    const int lane = tid & 31;
    const int wm   = tid >> 5;
    const int grp  = lane >> 2;
    const int tg   = lane & 3;

    const float* base = qkv + (size_t)bw * WIN * 1536 + h * 32;
    const float SCALE = 0.17677669529663687f;

    // ---- coalesced fills (float4) ----
    for (int l = tid; l < WIN * 8; l += 128) {
        int i = l >> 3, c = l & 7;
        const float* row = base + (size_t)i * 1536;
        float4 qv = *((const float4*)row + c);
        qv.x = tf32r(qv.x * SCALE); qv.y = tf32r(qv.y * SCALE);
        qv.z = tf32r(qv.z * SCALE); qv.w = tf32r(qv.w * SCALE);
        *(float4*)(Qs + i * QST + c * 4) = qv;
        float4 kv = *((const float4*)(row + 512) + c);
        kv.x = tf32r(kv.x); kv.y = tf32r(kv.y);
        kv.z = tf32r(kv.z); kv.w = tf32r(kv.w);
        *(float4*)(Ks + i * KST + c * 4) = kv;
        float4 vv = *((const float4*)(row + 1024) + c);
        vv.x = tf32r(vv.x); vv.y = tf32r(vv.y);
        vv.z = tf32r(vv.z); vv.w = tf32r(vv.w);
        *(float4*)(Vs + i * VST + c * 4) = vv;
    }
    // zero pad rows: Q rows 49..63, K/V rows 49..55
    const float4 z4 = make_float4(0.f, 0.f, 0.f, 0.f);
    for (int l = tid; l < 15 * 8; l += 128) {
        int i = WIN + (l >> 3), c = l & 7;
        *(float4*)(Qs + i * QST + c * 4) = z4;
        if (i < 56) {
            *(float4*)(Ks + i * KST + c * 4) = z4;
            *(float4*)(Vs + i * VST + c * 4) = z4;
        }
    }
    for (int l = tid; l < 169; l += 128) bs[l] = bias_table[l * HEADS + h];
    __syncthreads();

    const int i0 = wm * 16 + grp;
    const int i1 = i0 + 8;
    const int ri0 = div7(i0), ci0 = i0 - ri0 * 7;
    const int ri1 = div7(i1), ci1 = i1 - ri1 * 7;

    // ---- QK^T ----
    float c[7][4];
    #pragma unroll
    for (int nt = 0; nt < 7; nt++)
        #pragma unroll
        for (int l = 0; l < 4; l++) c[nt][l] = 0.f;

    #pragma unroll
    for (int ks = 0; ks < 4; ks++) {
        const int kk = ks * 8;
        unsigned a[4];
        a[0] = __float_as_uint(Qs[i0 * QST + kk + tg]);
        a[1] = __float_as_uint(Qs[i1 * QST + kk + tg]);
        a[2] = __float_as_uint(Qs[i0 * QST + kk + tg + 4]);
        a[3] = __float_as_uint(Qs[i1 * QST + kk + tg + 4]);
        #pragma unroll
        for (int nt = 0; nt < 7; nt++) {
            const int j = nt * 8 + grp;          // B fragment: K[j][d] row-major
            unsigned b[2];
            b[0] = __float_as_uint(Ks[j * KST + kk + tg]);
            b[1] = __float_as_uint(Ks[j * KST + kk + tg + 4]);
            mma_tf32(c[nt], a, b);
        }
    }

    // ---- softmax numerators -> Ps, row sums via tg-butterfly ----
    float s01 = 0.f, s23 = 0.f;
    #pragma unroll
    for (int nt = 0; nt < 7; nt++) {
        const int j0 = nt * 8 + 2 * tg;
        const int j1 = j0 + 1;
        const int rj0 = div7(j0), cj0 = j0 - rj0 * 7;
        const int rj1 = div7(j1), cj1 = j1 - rj1 * 7;
        float e00 = 0.f, e01 = 0.f, e10 = 0.f, e11 = 0.f;
        if (j0 < WIN) {
            e00 = __expf(c[nt][0] + bs[(ri0 - rj0 + 6) * 13 + (ci0 - cj0 + 6)]);
            e10 = __expf(c[nt][2] + bs[(ri1 - rj0 + 6) * 13 + (ci1 - cj0 + 6)]);
        }
        if (j1 < WIN) {
            e01 = __expf(c[nt][1] + bs[(ri0 - rj1 + 6) * 13 + (ci0 - cj1 + 6)]);
            e11 = __expf(c[nt][3] + bs[(ri1 - rj1 + 6) * 13 + (ci1 - cj1 + 6)]);
        }
        s01 += e00 + e01;
        s23 += e10 + e11;
        *(float2*)(Ps + i0 * PST + j0) = make_float2(tf32r(e00), tf32r(e01));
        *(float2*)(Ps + i1 * PST + j0) = make_float2(tf32r(e10), tf32r(e11));
    }
    s01 += __shfl_xor_sync(0xFFFFFFFFu, s01, 1);
    s01 += __shfl_xor_sync(0xFFFFFFFFu, s01, 2);
    s23 += __shfl_xor_sync(0xFFFFFFFFu, s23, 1);
    s23 += __shfl_xor_sync(0xFFFFFFFFu, s23, 2);
    if (tg == 0) {
        inv[i0] = 1.f / s01;
        inv[i1] = 1.f / s23;
    }
    __syncwarp();

    // ---- PV (P rows warp-local) ----
    float o[4][4];
    #pragma unroll
    for (int nt = 0; nt < 4; nt++)
        #pragma unroll
        for (int l = 0; l < 4; l++) o[nt][l] = 0.f;

    #pragma unroll
    for (int ks = 0; ks < 7; ks++) {
        const int kk = ks * 8;
        unsigned a[4];
        a[0] = __float_as_uint(Ps[i0 * PST + kk + tg]);
        a[1] = __float_as_uint(Ps[i1 * PST + kk + tg]);
        a[2] = __float_as_uint(Ps[i0 * PST + kk + tg + 4]);
        a[3] = __float_as_uint(Ps[i1 * PST + kk + tg + 4]);
        #pragma unroll
        for (int nt = 0; nt < 4; nt++) {
            unsigned b[2];
            b[0] = __float_as_uint(Vs[(kk + tg)     * VST + nt * 8 + grp]);
            b[1] = __float_as_uint(Vs[(kk + tg + 4) * VST + nt * 8 + grp]);
            mma_tf32(o[nt], a, b);
        }
    }

    const float v0 = inv[i0];
    const float v1 = inv[i1];
    float* obase = att + (size_t)bw * WIN * 512 + h * 32;
    #pragma unroll
    for (int nt = 0; nt < 4; nt++) {
        const int d0 = nt * 8 + 2 * tg;
        if (i0 < WIN)
            *(float2*)(obase + (size_t)i0 * 512 + d0) =
                make_float2(tf32r(o[nt][0] * v0), tf32r(o[nt][1] * v0));
        if (i1 < WIN)
            *(float2*)(obase + (size_t)i1 * 512 + d0) =
                make_float2(tf32r(o[nt][2] * v1), tf32r(o[nt][3] * v1));
    }
}

// --------------------------------- launcher --------------------------------
extern "C" void kernel_launch(void* const* d_in, const int* in_sizes, int n_in,
                              void* d_out, int out_size)
{
    const float* x          = (const float*)d_in[0];
    const float* w_qkv      = (const float*)d_in[1];
    const float* bias_table = (const float*)d_in[2];
    const float* w_out      = (const float*)d_in[3];
    float* out = (float*)d_out;

    float *qkv, *att, *xr, *wqkv_r, *wout_r;
    cudaGetSymbolAddress((void**)&qkv,    g_qkv);
    cudaGetSymbolAddress((void**)&att,    g_att);
    cudaGetSymbolAddress((void**)&xr,     g_xr);
    cudaGetSymbolAddress((void**)&wqkv_r, g_wqkv_r);
    cudaGetSymbolAddress((void**)&wout_r, g_wout_r);

    cudaFuncSetAttribute(gemm_tf32, cudaFuncAttributeMaxDynamicSharedMemorySize,
                         SMEM_FLOATS * 4);

    const long nreal = (long)M_REAL * 512;
    const long ntot  = (long)M_PAD  * 512;

    round_pad<<<(int)((ntot + 255) / 256), 256>>>(x, xr, nreal, ntot);
    round_copy<<<(786432 + 255) / 256, 256>>>(w_qkv, wqkv_r, 786432);
    round_copy<<<(262144 + 255) / 256, 256>>>(w_out, wout_r, 262144);
    zero_fill<<<(64 * 512 + 255) / 256, 256>>>(att + nreal, 64 * 512);

    // K1: qkv = xr @ wqkv_r
    gemm_tf32<<<dim3(1536 / BN, M_PAD / BM), 128, SMEM_FLOATS * 4>>>(
        xr, wqkv_r, qkv, M_REAL, 1536);

    // K2: attention (tensor-core QK^T and PV)
    attn_mma<<<NWIN * HEADS, 128>>>(qkv, bias_table, att);

    // K3: out = att @ wout_r
    gemm_tf32<<<dim3(512 / BN, M_PAD / BM), 128, SMEM_FLOATS * 4>>>(
        att, wout_r, out, M_REAL, 512);
}

// round 8
// speedup vs baseline: 2.0681x; 1.2954x over previous
#include <cuda_runtime.h>
#include <cuda_fp16.h>
#include <cstdint>

// ---------------------------------------------------------------------------
// MultiAxisAttention (Swin window attention) — fp16 HMMA GEMMs (m16n8k16,
// fp32 accumulate; fp16 u == tf32 u), tf32 HMMA attention (R7-proven).
//   prep: xh = half(x) (pad rows zeroed), weights transposed+half
//   K1:   qkvh = xh @ wqkvT^T   (fp16 mma, cp.async dbl-buffer)
//   K2:   attention (tf32 mma, half I/O)
//   K3:   out  = atth @ woutT^T (fp16 mma, fp32 output)
// ---------------------------------------------------------------------------

#define M_REAL 153664            // 16*196*49
#define M_PAD  153728            // 1201*128
#define NWIN   3136
#define HEADS  16
#define WIN    49
#define KDIM   512

__device__ __half g_qkvh[236027904];   // M_REAL*1536
__device__ __half g_atth[78708736];    // M_PAD*512 (pad rows zeroed)
__device__ __half g_xh  [78708736];    // M_PAD*512 (pad rows zeroed)
__device__ __half g_wqkvT[786432];     // [1536][512]
__device__ __half g_woutT[262144];     // [512][512]

// ------------------------------ helpers -----------------------------------
__device__ __forceinline__ float tf32r(float f) {
    unsigned u;
    asm("cvt.rna.tf32.f32 %0, %1;" : "=r"(u) : "f"(f));
    return __uint_as_float(u);
}
__device__ __forceinline__ uint32_t smem_u32(const void* p) {
    uint32_t a;
    asm("{ .reg .u64 t; cvta.to.shared.u64 t, %1; cvt.u32.u64 %0, t; }"
        : "=r"(a) : "l"(p));
    return a;
}
__device__ __forceinline__ void cp16(uint32_t dst, const void* src) {
    asm volatile("cp.async.cg.shared.global [%0], [%1], 16;\n"
                 :: "r"(dst), "l"(src));
}
#define CP_COMMIT() asm volatile("cp.async.commit_group;\n" ::: "memory")
#define CP_WAIT(n)  asm volatile("cp.async.wait_group %0;\n" :: "n"(n) : "memory")

__device__ __forceinline__ void mma_f16(float* d, const unsigned* a, const unsigned* b) {
    asm volatile(
        "mma.sync.aligned.m16n8k16.row.col.f32.f16.f16.f32 "
        "{%0,%1,%2,%3}, {%4,%5,%6,%7}, {%8,%9}, {%0,%1,%2,%3};\n"
        : "+f"(d[0]), "+f"(d[1]), "+f"(d[2]), "+f"(d[3])
        : "r"(a[0]), "r"(a[1]), "r"(a[2]), "r"(a[3]),
          "r"(b[0]), "r"(b[1]));
}
__device__ __forceinline__ void mma_tf32(float* d, const unsigned* a, const unsigned* b) {
    asm volatile(
        "mma.sync.aligned.m16n8k8.row.col.f32.tf32.tf32.f32 "
        "{%0,%1,%2,%3}, {%4,%5,%6,%7}, {%8,%9}, {%0,%1,%2,%3};\n"
        : "+f"(d[0]), "+f"(d[1]), "+f"(d[2]), "+f"(d[3])
        : "r"(a[0]), "r"(a[1]), "r"(a[2]), "r"(a[3]),
          "r"(b[0]), "r"(b[1]));
}

// epilogue store: float2 vs half2
__device__ __forceinline__ void storeC(float* C, size_t idx, float a, float b) {
    *(float2*)(C + idx) = make_float2(a, b);
}
__device__ __forceinline__ void storeC(__half* C, size_t idx, float a, float b) {
    *(__half2*)(C + idx) = __floats2half2_rn(a, b);
}

// ----------------------------- GEMM (fp16) ---------------------------------
// block 128x128, BK=32(k16 x2), 4 warps (2x2), warp tile 64x64.
// A: [M][512] half row-major.  B: WT [N][512] half row-major (pre-transposed).
// smem rows padded to 40 halves (20 words): fragment banks 20*grp+tg distinct.
#define BM 128
#define BN 128
#define BK 32
#define RSH 40                        // halves per smem row
#define OP_HALVES (128 * RSH)         // 5120 per operand per stage
#define STG_HALVES (2 * OP_HALVES)    // 10240 per stage (A|B)

template <typename OutT>
__global__ void __launch_bounds__(128)
gemm_f16(const __half* __restrict__ A, const __half* __restrict__ B,
         OutT* __restrict__ C, int Mreal, int N)
{
    __shared__ __half sm[2 * STG_HALVES];   // 40 KB

    const int tid  = threadIdx.x;
    const int lane = tid & 31;
    const int warp = tid >> 5;
    const int wm   = warp >> 1;
    const int wn   = warp & 1;
    const int grp  = lane >> 2;
    const int tg   = lane & 3;

    const int m0 = blockIdx.y * BM;
    const int n0 = blockIdx.x * BN;

    // fill geometry: row = 8*warp + (lane>>2) + 32p (p<4), chunk = lane&3 (16B)
    const int frow = 8 * warp + (lane >> 2);
    const int fchk = (lane & 3) << 3;          // halves: 0,8,16,24
    const __half*  ag0 = A + (size_t)(m0 + frow) * KDIM + fchk;
    const __half*  bg0 = B + (size_t)(n0 + frow) * KDIM + fchk;
    const uint32_t smb = smem_u32(sm);
    const uint32_t adst0 = smb + (uint32_t)(frow * RSH + fchk) * 2;
    const uint32_t bdst0 = adst0 + OP_HALVES * 2;

    float acc[4][8][4];
    #pragma unroll
    for (int i = 0; i < 4; i++)
        #pragma unroll
        for (int j = 0; j < 8; j++)
            #pragma unroll
            for (int l = 0; l < 4; l++) acc[i][j][l] = 0.f;

    const int T = KDIM / BK;   // 16

    #pragma unroll
    for (int p = 0; p < 4; p++) {
        cp16(adst0 + (uint32_t)(p * 32 * RSH) * 2, ag0 + (size_t)p * 32 * KDIM);
        cp16(bdst0 + (uint32_t)(p * 32 * RSH) * 2, bg0 + (size_t)p * 32 * KDIM);
    }
    CP_COMMIT();

    for (int t = 0; t < T; ++t) {
        const int buf = t & 1;

        if (t + 1 < T) {
            const int nb = (t + 1) & 1;
            const int kb = (t + 1) * BK;
            const uint32_t ad = adst0 + (uint32_t)(nb * STG_HALVES) * 2;
            const uint32_t bd = bdst0 + (uint32_t)(nb * STG_HALVES) * 2;
            const __half* ag = ag0 + kb;
            const __half* bg = bg0 + kb;
            #pragma unroll
            for (int p = 0; p < 4; p++) {
                cp16(ad + (uint32_t)(p * 32 * RSH) * 2, ag + (size_t)p * 32 * KDIM);
                cp16(bd + (uint32_t)(p * 32 * RSH) * 2, bg + (size_t)p * 32 * KDIM);
            }
            CP_COMMIT();
            CP_WAIT(1);
        } else {
            CP_WAIT(0);
        }
        __syncthreads();

        const __half* Ab = sm + buf * STG_HALVES;
        const __half* Bb = Ab + OP_HALVES;
        #pragma unroll
        for (int ks = 0; ks < 2; ks++) {
            const int kk = ks * 16;            // halves
            unsigned af[4][4], bf[8][2];
            #pragma unroll
            for (int mt = 0; mt < 4; mt++) {
                int mr = wm * 64 + mt * 16 + grp;
                const __half* ra = Ab + mr * RSH + kk + 2 * tg;
                af[mt][0] = *(const unsigned*)(ra);
                af[mt][1] = *(const unsigned*)(ra + 8 * RSH);
                af[mt][2] = *(const unsigned*)(ra + 8);
                af[mt][3] = *(const unsigned*)(ra + 8 * RSH + 8);
            }
            #pragma unroll
            for (int nt = 0; nt < 8; nt++) {
                int nc = wn * 64 + nt * 8 + grp;
                const __half* rb = Bb + nc * RSH + kk + 2 * tg;
                bf[nt][0] = *(const unsigned*)(rb);
                bf[nt][1] = *(const unsigned*)(rb + 8);
            }
            #pragma unroll
            for (int mt = 0; mt < 4; mt++)
                #pragma unroll
                for (int nt = 0; nt < 8; nt++)
                    mma_f16(acc[mt][nt], af[mt], bf[nt]);
        }
        __syncthreads();
    }

    #pragma unroll
    for (int mt = 0; mt < 4; mt++) {
        #pragma unroll
        for (int nt = 0; nt < 8; nt++) {
            int r0 = m0 + wm * 64 + mt * 16 + grp;
            int c  = n0 + wn * 64 + nt * 8 + tg * 2;
            if (r0 < Mreal)
                storeC(C, (size_t)r0 * N + c, acc[mt][nt][0], acc[mt][nt][1]);
            if (r0 + 8 < Mreal)
                storeC(C, (size_t)(r0 + 8) * N + c, acc[mt][nt][2], acc[mt][nt][3]);
        }
    }
}

// ------------------------------ prep kernels -------------------------------
__global__ void half_pad(const float* __restrict__ x, __half* __restrict__ xh,
                         long nreal, long ntot)
{
    long i = (long)blockIdx.x * blockDim.x + threadIdx.x;
    if (i < ntot) xh[i] = __float2half((i < nreal) ? x[i] : 0.f);
}

// W [R][Ccols] f32 -> WT [Ccols][R] half
__global__ void transpose_half(const float* __restrict__ W, __half* __restrict__ WT,
                               int R, int Ccols)
{
    __shared__ float t[32][33];
    const int tx = threadIdx.x, ty = threadIdx.y;
    const int x = blockIdx.x * 32 + tx;
    #pragma unroll
    for (int j = 0; j < 4; j++) {
        int y = blockIdx.y * 32 + ty + j * 8;
        t[ty + j * 8][tx] = W[(size_t)y * Ccols + x];
    }
    __syncthreads();
    const int ox = blockIdx.y * 32 + tx;
    #pragma unroll
    for (int j = 0; j < 4; j++) {
        int oy = blockIdx.x * 32 + ty + j * 8;
        WT[(size_t)oy * R + ox] = __float2half(t[tx][ty + j * 8]);
    }
}

__global__ void zero_fill_h(__half* __restrict__ p, int n)   // n halves, even
{
    int i = blockIdx.x * blockDim.x + threadIdx.x;
    if (i < n / 2) ((uint32_t*)p)[i] = 0u;
}

// ----------------------------- attention (tf32 HMMA, half I/O) -------------
#define QST 36
#define KST 36
#define VST 40
#define PST 60

__device__ __forceinline__ int div7(int v) { return (v * 37) >> 8; }  // exact 0..55

__global__ void __launch_bounds__(128)
attn_mma(const __half* __restrict__ qkv,
         const float* __restrict__ bias_table,
         __half* __restrict__ att)
{
    __shared__ float Qs[64 * QST];
    __shared__ float Ks[56 * KST];
    __shared__ float Vs[56 * VST];
    __shared__ float Ps[64 * PST];
    __shared__ float bs[176];
    __shared__ float inv[64];

    const int h  = blockIdx.x & 15;
    const int bw = blockIdx.x >> 4;
    const int tid  = threadIdx.x;
    const int lane = tid & 31;
    const int wm   = tid >> 5;
    const int grp  = lane >> 2;
    const int tg   = lane & 3;

    const __half* base = qkv + (size_t)bw * WIN * 1536 + h * 32;
    const float SCALE = 0.17677669529663687f;

    // ---- coalesced fills: 8 halves per (i,c) ----
    for (int l = tid; l < WIN * 4; l += 128) {
        int i = l >> 2, c = l & 3;
        const __half2* qrow = (const __half2*)(base + (size_t)i * 1536) + c * 4;
        const __half2* krow = (const __half2*)(base + (size_t)i * 1536 + 512) + c * 4;
        const __half2* vrow = (const __half2*)(base + (size_t)i * 1536 + 1024) + c * 4;
        #pragma unroll
        for (int q = 0; q < 4; q++) {
            float2 qf = __half22float2(qrow[q]);
            Qs[i * QST + c * 8 + 2 * q]     = tf32r(qf.x * SCALE);
            Qs[i * QST + c * 8 + 2 * q + 1] = tf32r(qf.y * SCALE);
            float2 kf = __half22float2(krow[q]);       // exact in tf32
            Ks[i * KST + c * 8 + 2 * q]     = kf.x;
            Ks[i * KST + c * 8 + 2 * q + 1] = kf.y;
            float2 vf = __half22float2(vrow[q]);
            Vs[i * VST + c * 8 + 2 * q]     = vf.x;
            Vs[i * VST + c * 8 + 2 * q + 1] = vf.y;
        }
    }
    // zero pad rows: Q rows 49..63, K/V rows 49..55
    const float4 z4 = make_float4(0.f, 0.f, 0.f, 0.f);
    for (int l = tid; l < 15 * 8; l += 128) {
        int i = WIN + (l >> 3), c = l & 7;
        *(float4*)(Qs + i * QST + c * 4) = z4;
        if (i < 56) {
            *(float4*)(Ks + i * KST + c * 4) = z4;
            *(float4*)(Vs + i * VST + c * 4) = z4;
        }
    }
    for (int l = tid; l < 169; l += 128) bs[l] = bias_table[l * HEADS + h];
    __syncthreads();

    const int i0 = wm * 16 + grp;
    const int i1 = i0 + 8;
    const int ri0 = div7(i0), ci0 = i0 - ri0 * 7;
    const int ri1 = div7(i1), ci1 = i1 - ri1 * 7;

    // ---- QK^T ----
    float c[7][4];
    #pragma unroll
    for (int nt = 0; nt < 7; nt++)
        #pragma unroll
        for (int l = 0; l < 4; l++) c[nt][l] = 0.f;

    #pragma unroll
    for (int ks = 0; ks < 4; ks++) {
        const int kk = ks * 8;
        unsigned a[4];
        a[0] = __float_as_uint(Qs[i0 * QST + kk + tg]);
        a[1] = __float_as_uint(Qs[i1 * QST + kk + tg]);
        a[2] = __float_as_uint(Qs[i0 * QST + kk + tg + 4]);
        a[3] = __float_as_uint(Qs[i1 * QST + kk + tg + 4]);
        #pragma unroll
        for (int nt = 0; nt < 7; nt++) {
            const int j = nt * 8 + grp;
            unsigned b[2];
            b[0] = __float_as_uint(Ks[j * KST + kk + tg]);
            b[1] = __float_as_uint(Ks[j * KST + kk + tg + 4]);
            mma_tf32(c[nt], a, b);
        }
    }

    // ---- softmax numerators -> Ps, row sums via tg-butterfly ----
    float s01 = 0.f, s23 = 0.f;
    #pragma unroll
    for (int nt = 0; nt < 7; nt++) {
        const int j0 = nt * 8 + 2 * tg;
        const int j1 = j0 + 1;
        const int rj0 = div7(j0), cj0 = j0 - rj0 * 7;
        const int rj1 = div7(j1), cj1 = j1 - rj1 * 7;
        float e00 = 0.f, e01 = 0.f, e10 = 0.f, e11 = 0.f;
        if (j0 < WIN) {
            e00 = __expf(c[nt][0] + bs[(ri0 - rj0 + 6) * 13 + (ci0 - cj0 + 6)]);
            e10 = __expf(c[nt][2] + bs[(ri1 - rj0 + 6) * 13 + (ci1 - cj0 + 6)]);
        }
        if (j1 < WIN) {
            e01 = __expf(c[nt][1] + bs[(ri0 - rj1 + 6) * 13 + (ci0 - cj1 + 6)]);
            e11 = __expf(c[nt][3] + bs[(ri1 - rj1 + 6) * 13 + (ci1 - cj1 + 6)]);
        }
        s01 += e00 + e01;
        s23 += e10 + e11;
        *(float2*)(Ps + i0 * PST + j0) = make_float2(tf32r(e00), tf32r(e01));
        *(float2*)(Ps + i1 * PST + j0) = make_float2(tf32r(e10), tf32r(e11));
    }
    s01 += __shfl_xor_sync(0xFFFFFFFFu, s01, 1);
    s01 += __shfl_xor_sync(0xFFFFFFFFu, s01, 2);
    s23 += __shfl_xor_sync(0xFFFFFFFFu, s23, 1);
    s23 += __shfl_xor_sync(0xFFFFFFFFu, s23, 2);
    if (tg == 0) {
        inv[i0] = 1.f / s01;
        inv[i1] = 1.f / s23;
    }
    __syncwarp();

    // ---- PV ----
    float o[4][4];
    #pragma unroll
    for (int nt = 0; nt < 4; nt++)
        #pragma unroll
        for (int l = 0; l < 4; l++) o[nt][l] = 0.f;

    #pragma unroll
    for (int ks = 0; ks < 7; ks++) {
        const int kk = ks * 8;
        unsigned a[4];
        a[0] = __float_as_uint(Ps[i0 * PST + kk + tg]);
        a[1] = __float_as_uint(Ps[i1 * PST + kk + tg]);
        a[2] = __float_as_uint(Ps[i0 * PST + kk + tg + 4]);
        a[3] = __float_as_uint(Ps[i1 * PST + kk + tg + 4]);
        #pragma unroll
        for (int nt = 0; nt < 4; nt++) {
            unsigned b[2];
            b[0] = __float_as_uint(Vs[(kk + tg)     * VST + nt * 8 + grp]);
            b[1] = __float_as_uint(Vs[(kk + tg + 4) * VST + nt * 8 + grp]);
            mma_tf32(o[nt], a, b);
        }
    }

    const float v0 = inv[i0];
    const float v1 = inv[i1];
    __half* obase = att + (size_t)bw * WIN * 512 + h * 32;
    #pragma unroll
    for (int nt = 0; nt < 4; nt++) {
        const int d0 = nt * 8 + 2 * tg;
        if (i0 < WIN)
            *(__half2*)(obase + (size_t)i0 * 512 + d0) =
                __floats2half2_rn(o[nt][0] * v0, o[nt][1] * v0);
        if (i1 < WIN)
            *(__half2*)(obase + (size_t)i1 * 512 + d0) =
                __floats2half2_rn(o[nt][2] * v1, o[nt][3] * v1);
    }
}

// --------------------------------- launcher --------------------------------
extern "C" void kernel_launch(void* const* d_in, const int* in_sizes, int n_in,
                              void* d_out, int out_size)
{
    const float* x          = (const float*)d_in[0];
    const float* w_qkv      = (const float*)d_in[1];
    const float* bias_table = (const float*)d_in[2];
    const float* w_out      = (const float*)d_in[3];
    float* out = (float*)d_out;

    __half *qkvh, *atth, *xh, *wqkvT, *woutT;
    cudaGetSymbolAddress((void**)&qkvh,  g_qkvh);
    cudaGetSymbolAddress((void**)&atth,  g_atth);
    cudaGetSymbolAddress((void**)&xh,    g_xh);
    cudaGetSymbolAddress((void**)&wqkvT, g_wqkvT);
    cudaGetSymbolAddress((void**)&woutT, g_woutT);

    const long nreal = (long)M_REAL * 512;
    const long ntot  = (long)M_PAD  * 512;

    half_pad<<<(int)((ntot + 255) / 256), 256>>>(x, xh, nreal, ntot);
    transpose_half<<<dim3(1536 / 32, 512 / 32), dim3(32, 8)>>>(w_qkv, wqkvT, 512, 1536);
    transpose_half<<<dim3(512 / 32, 512 / 32), dim3(32, 8)>>>(w_out, woutT, 512, 512);
    zero_fill_h<<<(64 * 512 / 2 + 255) / 256, 256>>>(atth + nreal, 64 * 512);

    // K1: qkvh = xh @ wqkvT^T
    gemm_f16<__half><<<dim3(1536 / BN, M_PAD / BM), 128>>>(
        xh, wqkvT, qkvh, M_REAL, 1536);

    // K2: attention
    attn_mma<<<NWIN * HEADS, 128>>>(qkvh, bias_table, atth);

    // K3: out = atth @ woutT^T
    gemm_f16<float><<<dim3(512 / BN, M_PAD / BM), 128>>>(
        atth, woutT, out, M_REAL, 512);
}